// round 4
// baseline (speedup 1.0000x reference)
#include <cuda_runtime.h>

// Problem constants (fixed by setup_inputs)
#define B     128
#define NPIX  2048
#define NBINS 1500
#define NBF   250
#define NREP  256
#define LGS   1251   // n_bins - n_bins_filter + 1
#define TSIM  1250   // len_bins_sim
#define NBLK  40     // ceil(TSIM/32)

// Scratch (device globals; no dynamic allocation allowed)
__device__ __align__(16) float g_filt_spat[B];
__device__ __align__(16) float g_filt_time[LGS + 1];
__device__ __align__(16) float g_timeline[B * NBINS];  // [b][0..249]=init, [b][250+t]=spike_t
__device__ __align__(16) float g_gensig[B * TSIM];

__device__ __forceinline__ float fsig(float x) {
    // 1/(1+exp(-x)) via MUFU ex2 + rcp (rel err ~1e-6, well under 1e-3 tolerance)
    return __fdividef(1.0f, 1.0f + __expf(-x));
}

// ---------------------------------------------------------------------------
// Phase 1a: filt_spat[b] = dot(A[b, :], sf)   (128 blocks x 256 threads)
// ---------------------------------------------------------------------------
__global__ void k_spat(const float* __restrict__ A, const float* __restrict__ sf) {
    __shared__ float red[256];
    int b = blockIdx.x, tid = threadIdx.x;
    const float* row = A + (size_t)b * NPIX;
    float s = 0.f;
    #pragma unroll
    for (int p = tid; p < NPIX; p += 256) s += row[p] * sf[p];
    red[tid] = s;
    __syncthreads();
    for (int o = 128; o > 0; o >>= 1) {
        if (tid < o) red[tid] += red[tid + o];
        __syncthreads();
    }
    if (tid == 0) g_filt_spat[b] = red[0];
}

// ---------------------------------------------------------------------------
// Phase 1b: filt_time[t] = sum_j stim_time[t+j] * tf[j]  (valid correlation)
// ---------------------------------------------------------------------------
__global__ void k_time(const float* __restrict__ st, const float* __restrict__ tf) {
    __shared__ float shtf[NBF];
    int tid = threadIdx.x;
    for (int j = tid; j < NBF; j += 128) shtf[j] = tf[j];
    __syncthreads();
    int t = blockIdx.x * 128 + tid;
    if (t < LGS) {
        float s = 0.f;
        #pragma unroll 5
        for (int j = 0; j < NBF; j++) s += st[t + j] * shtf[j];
        g_filt_time[t] = s;
    }
}

// ---------------------------------------------------------------------------
// Phase 2: per-batch serial recurrence. 128 blocks x 64 threads.
//   warp 0: serial chain, 32 time steps per block-iteration (lane i owns T0+i)
//   warp 1: pipelined precompute of next block's history-only partials
//
// Timeline coords: tl[k]=init[k] for k<250, tl[250+t]=spike_t.
// fb_t = sum_{j=0..249} tl[t+j] * f[j].
// For block at T0, lane i (t=T0+i):
//   - taps j in [0, 217-i]  : known two blocks back  -> warp-1 precompute
//   - taps j in [218-i,249-i]: previous block spikes -> 32-tap fixup by warp 0
//   - taps j in [250-i,249] : in-block spikes        -> serial shfl updates
// ---------------------------------------------------------------------------
__global__ __launch_bounds__(64, 1) void k_recur(const float* __restrict__ init,
                                                 const float* __restrict__ fbf,
                                                 const float* __restrict__ bias) {
    __shared__ float sh_tl[1504];
    __shared__ float sh_f[288];      // [250..287] zero-padded -> branch-free serial FMA
    __shared__ float sh_g[1280];     // g_t = filt_spat[b]*filt_time[t] + bias, zero-padded
    __shared__ float sh_pre[2][32];

    int b = blockIdx.x, tid = threadIdx.x;
    int warp = tid >> 5, lane = tid & 31;

    // --- init shared state (both warps) ---
    for (int j = tid; j < NBF; j += 64) {
        float v = init[b * NBF + j];
        sh_tl[j] = v;
        g_timeline[(size_t)b * NBINS + j] = v;
        sh_f[j] = fbf[j];
    }
    for (int j = NBF + tid; j < 288; j += 64) sh_f[j] = 0.f;
    float fs = g_filt_spat[b];
    float bv = bias[0];
    for (int j = tid; j < 1280; j += 64)
        sh_g[j] = (j < TSIM) ? fs * g_filt_time[j] + bv : 0.f;
    __syncthreads();

    // Block 0 full precompute (all taps are initial history)
    if (warp == 0) {
        int i = lane;
        float acc = 0.f;
        for (int j = 0; j < NBF; j++)
            if (j < NBF - i) acc += sh_tl[i + j] * sh_f[j];
        sh_pre[0][i] = acc;
    }

    for (int m = 0; m < NBLK; m++) {
        __syncthreads();   // sh_pre[m&1] ready; timeline through block m-1 ready
        int T0 = m * 32;

        if (warp == 0) {
            int i = lane, t = T0 + i;
            float part = sh_pre[m & 1][i] + sh_g[t];

            if (m > 0) {
                // fixup: previous block's 32 spikes, tl[250+T0-32 .. 250+T0-1]
                int base = 250 + T0 - 32;
                #pragma unroll
                for (int k = 0; k < 32; k++)
                    part += sh_tl[base + k] * sh_f[218 - i + k];
            }

            float sp = 0.f, gs = 0.f;
            int kmax = TSIM - T0; if (kmax > 32) kmax = 32;

            if (kmax == 32) {
                #pragma unroll
                for (int k = 0; k < 32; k++) {
                    float fv = sh_f[250 - i + k];     // zero when i <= k (padding)
                    if (i == k) { gs = part; sp = fsig(part); }
                    float s = __shfl_sync(0xffffffffu, sp, k);
                    part += s * fv;
                }
            } else {
                for (int k = 0; k < kmax; k++) {
                    float fv = sh_f[250 - i + k];
                    if (i == k) { gs = part; sp = fsig(part); }
                    float s = __shfl_sync(0xffffffffu, sp, k);
                    part += s * fv;
                }
            }

            if (i < kmax) {
                sh_tl[250 + t] = sp;
                g_timeline[(size_t)b * NBINS + 250 + t] = sp;
                g_gensig[(size_t)b * TSIM + t] = gs;
            }
        } else {
            // warp 1: precompute block m+1 partials over history < 250+T0
            if (m + 1 < NBLK) {
                int i = lane, T0n = T0 + 32;
                float acc = 0.f;
                int lim = 218 - i;
                for (int j = 0; j < lim; j++)
                    acc += sh_tl[T0n + i + j] * sh_f[j];
                sh_pre[(m + 1) & 1][i] = acc;
            }
        }
    }
}

// ---------------------------------------------------------------------------
// Phase 3: broadcast writer. One block per (b, r). Sources are L1/L2 resident.
//   out[0 .. B*R*1500)            = output_bins_acc[b][r][:] = timeline[b][:]
//   out[B*R*1500 .. +B*R*1250)    = gensigs[b][r][:]         = gensig[b][:]
// ---------------------------------------------------------------------------
__global__ void k_write(float* __restrict__ out, long out_size) {
    long blk = blockIdx.x;                 // b*NREP + r
    int b = (int)(blk >> 8);               // NREP = 256
    int tid = threadIdx.x;

    long base1 = blk * NBINS;
    if (base1 + NBINS <= out_size) {
        const float4* src1 = (const float4*)(g_timeline + (size_t)b * NBINS);
        float4* dst1 = (float4*)(out + base1);
        #pragma unroll
        for (int i = tid; i < NBINS / 4; i += 256) dst1[i] = src1[i];  // 375 vec4
    }

    long n1 = (long)B * NREP * NBINS;
    long base2 = n1 + blk * TSIM;
    if (base2 + TSIM <= out_size) {
        const float2* src2 = (const float2*)(g_gensig + (size_t)b * TSIM);
        float2* dst2 = (float2*)(out + base2);
        #pragma unroll
        for (int i = tid; i < TSIM / 2; i += 256) dst2[i] = src2[i];   // 625 vec2
    }
}

// ---------------------------------------------------------------------------
extern "C" void kernel_launch(void* const* d_in, const int* in_sizes, int n_in,
                              void* d_out, int out_size) {
    const float* A    = (const float*)d_in[0];  // (128, 2048)
    const float* st   = (const float*)d_in[1];  // (1500,)
    const float* init = (const float*)d_in[2];  // (128, 250)
    // n_repeats may or may not appear as input index 3 (scalar). Detect.
    int off = (n_in >= 8) ? 1 : 0;
    const float* sf = (const float*)d_in[3 + off];  // (2048,)
    const float* tf = (const float*)d_in[4 + off];  // (250,)
    const float* fb = (const float*)d_in[5 + off];  // (250,)
    const float* bi = (const float*)d_in[6 + off];  // (1,)

    k_spat<<<B, 256>>>(A, sf);
    k_time<<<(LGS + 127) / 128, 128>>>(st, tf);
    k_recur<<<B, 64>>>(init, fb, bi);
    k_write<<<B * NREP, 256>>>((float*)d_out, (long)out_size);
}

// round 5
// speedup vs baseline: 1.0713x; 1.0713x over previous
#include <cuda_runtime.h>

// Problem constants (fixed by setup_inputs)
#define B     128
#define NPIX  2048
#define NBINS 1500
#define NBF   250
#define NREP  256
#define LGS   1251   // n_bins - n_bins_filter + 1
#define TSIM  1250   // len_bins_sim
#define NBLK  40     // ceil(TSIM/32)
#define N1    ((size_t)B * NREP * NBINS)   // start of gensig region in d_out

// Scratch (device globals; no dynamic allocation allowed)
__device__ float g_filt_spat[B];
__device__ float g_filt_time[LGS + 1];

__device__ __forceinline__ float fsig(float x) {
    // 1/(1+exp(-x)) via MUFU ex2 + rcp (rel err ~1e-6)
    return __fdividef(1.0f, 1.0f + __expf(-x));
}

// ---------------------------------------------------------------------------
// Phase 1a: filt_spat[b] = dot(A[b, :], sf)
// ---------------------------------------------------------------------------
__global__ void k_spat(const float* __restrict__ A, const float* __restrict__ sf) {
    __shared__ float red[256];
    int b = blockIdx.x, tid = threadIdx.x;
    const float* row = A + (size_t)b * NPIX;
    float s = 0.f;
    #pragma unroll
    for (int p = tid; p < NPIX; p += 256) s += row[p] * sf[p];
    red[tid] = s;
    __syncthreads();
    for (int o = 128; o > 0; o >>= 1) {
        if (tid < o) red[tid] += red[tid + o];
        __syncthreads();
    }
    if (tid == 0) g_filt_spat[b] = red[0];
}

// ---------------------------------------------------------------------------
// Phase 1b: filt_time[t] = valid cross-correlation of stim_time with tf
// ---------------------------------------------------------------------------
__global__ void k_time(const float* __restrict__ st, const float* __restrict__ tf) {
    __shared__ float shtf[NBF];
    int tid = threadIdx.x;
    for (int j = tid; j < NBF; j += 128) shtf[j] = tf[j];
    __syncthreads();
    int t = blockIdx.x * 128 + tid;
    if (t < LGS) {
        float s = 0.f;
        #pragma unroll 5
        for (int j = 0; j < NBF; j++) s += st[t + j] * shtf[j];
        g_filt_time[t] = s;
    }
}

// ---------------------------------------------------------------------------
// Phase 2+3 FUSED: per-batch serial recurrence + overlapped broadcast writer.
// 128 blocks x 256 threads (8 warps):
//   warp 0   : serial chain, 32 time steps per block-iteration (lane i owns T0+i)
//   warp 1   : pipelined precompute of next block's history-only partials
//   warps 2-7: broadcast segment m-1 (32 spikes + 32 gensigs x 256 repeats)
//              directly into d_out while warp 0 computes segment m.
//
// Timeline coords: tl[k]=init[k] for k<250, tl[250+t]=spike_t.
// fb_t = sum_{j=0..249} tl[t+j] * f[j].
// For block at T0, lane i (t=T0+i):
//   - taps j in [0, 217-i]   : spikes through block m-2 -> warp-1 precompute
//   - taps j in [218-i,249-i]: block m-1 spikes         -> 32-tap register fixup
//   - taps j in [250-i,249]  : in-block spikes          -> serial shfl chain
// ---------------------------------------------------------------------------
__global__ __launch_bounds__(256, 1) void k_recur(const float* __restrict__ init,
                                                  const float* __restrict__ fbf,
                                                  const float* __restrict__ bias,
                                                  float* __restrict__ out) {
    __shared__ __align__(16) float sh_tl[1504];   // timeline (init + spikes)
    __shared__ __align__(16) float sh_f[288];     // filter, zero-padded [250..287]
    __shared__ __align__(16) float sh_g[1280];    // drive g_t; overwritten with gensig_t
    __shared__ float sh_pre[2][32];

    int b = blockIdx.x, tid = threadIdx.x;
    int warp = tid >> 5, lane = tid & 31;
    float* outG = out + N1;

    // --- setup ---
    if (tid < NBF) { sh_tl[tid] = init[b * NBF + tid]; sh_f[tid] = fbf[tid]; }
    else if (tid < 288) sh_f[tid] = 0.f;
    {
        float fs = g_filt_spat[b], bv = bias[0];
        for (int j = tid; j < 1280; j += 256)
            sh_g[j] = (j < TSIM) ? fmaf(fs, g_filt_time[j], bv) : 0.f;
    }
    __syncthreads();

    float fv[32], fr[32];   // statically indexed only (keep in registers)
    if (warp == 0) {
        #pragma unroll
        for (int k = 0; k < 32; k++) {
            fv[k] = sh_f[250 - lane + k];   // zero for k >= lane
            fr[k] = sh_f[218 - lane + k];
        }
        // block-0 precompute: all taps from initial history (j < 250-lane)
        int lim = 250 - lane;
        float a0 = 0, a1 = 0, a2 = 0, a3 = 0;
        int j = 0;
        for (; j + 4 <= lim; j += 4) {
            a0 = fmaf(sh_tl[lane + j],     sh_f[j],     a0);
            a1 = fmaf(sh_tl[lane + j + 1], sh_f[j + 1], a1);
            a2 = fmaf(sh_tl[lane + j + 2], sh_f[j + 2], a2);
            a3 = fmaf(sh_tl[lane + j + 3], sh_f[j + 3], a3);
        }
        for (; j < lim; j++) a0 = fmaf(sh_tl[lane + j], sh_f[j], a0);
        sh_pre[0][lane] = (a0 + a1) + (a2 + a3);
    }

    for (int m = 0; m < NBLK; m++) {
        __syncthreads();   // sh_pre[m&1], timeline/gensig through block m-1 ready
        int T0 = m * 32;

        if (warp == 0) {
            int t = T0 + lane;
            float part = sh_pre[m & 1][lane] + sh_g[t];

            if (m > 0) {
                // fixup: previous block's 32 spikes (broadcast LDS x reg taps)
                int base = 250 + T0 - 32;
                float a0 = 0, a1 = 0, a2 = 0, a3 = 0;
                #pragma unroll
                for (int k = 0; k < 32; k += 4) {
                    a0 = fmaf(sh_tl[base + k],     fr[k],     a0);
                    a1 = fmaf(sh_tl[base + k + 1], fr[k + 1], a1);
                    a2 = fmaf(sh_tl[base + k + 2], fr[k + 2], a2);
                    a3 = fmaf(sh_tl[base + k + 3], fr[k + 3], a3);
                }
                part += (a0 + a1) + (a2 + a3);
            }

            int kmax = TSIM - T0; if (kmax > 32) kmax = 32;
            if (kmax == 32) {
                // branchless chain: every lane evaluates sigmoid; shfl picks lane k.
                // fv[k]==0 for k>=lane, so each lane's part freezes at its own step.
                #pragma unroll
                for (int k = 0; k < 32; k++) {
                    float cand = fsig(part);
                    float s = __shfl_sync(0xffffffffu, cand, k);
                    part = fmaf(s, fv[k], part);
                }
            } else {
                for (int k = 0; k < kmax; k++) {   // only m=39 (kmax=2)
                    float cand = fsig(part);
                    float s = __shfl_sync(0xffffffffu, cand, k);
                    part = fmaf(s, sh_f[250 - lane + k], part);
                }
            }

            if (lane < kmax) {
                sh_tl[250 + t] = fsig(part);   // spike_t
                sh_g[t] = part;                // gensig_t (drive already consumed)
            }
        } else if (warp == 1) {
            // precompute block m+1 partials over spikes through block m-1
            if (m + 1 < NBLK) {
                int T0n = T0 + 32;
                int lim = 218 - lane;
                float a0 = 0, a1 = 0, a2 = 0, a3 = 0;
                int j = 0;
                for (; j + 4 <= lim; j += 4) {
                    a0 = fmaf(sh_tl[T0n + lane + j],     sh_f[j],     a0);
                    a1 = fmaf(sh_tl[T0n + lane + j + 1], sh_f[j + 1], a1);
                    a2 = fmaf(sh_tl[T0n + lane + j + 2], sh_f[j + 2], a2);
                    a3 = fmaf(sh_tl[T0n + lane + j + 3], sh_f[j + 3], a3);
                }
                for (; j < lim; j++) a0 = fmaf(sh_tl[T0n + lane + j], sh_f[j], a0);
                sh_pre[(m + 1) & 1][lane] = (a0 + a1) + (a2 + a3);
            }
        } else {
            // copy warps: broadcast segment m-1 to all 256 repeats
            int cw = warp - 2;      // 0..5
            int seg = m - 1;
            if (seg < 0) {
                // init section: 250 floats = 125 float2 per repeat
                const float2* src = (const float2*)sh_tl;
                int e0 = lane, e1 = lane + 32, e2 = lane + 64, e3 = lane + 96;
                float2 v0 = src[e0], v1 = src[e1], v2 = src[e2];
                float2 v3; if (e3 < 125) v3 = src[e3];
                for (int r = cw; r < NREP; r += 6) {
                    float2* dst = (float2*)(out + ((size_t)(b * NREP + r)) * NBINS);
                    dst[e0] = v0; dst[e1] = v1; dst[e2] = v2;
                    if (e3 < 125) dst[e3] = v3;
                }
            } else {
                int tb = 250 + seg * 32;   // timeline float offset (even -> float2 ok)
                int gb = seg * 32;
                float2 v;
                if (lane < 16) v = ((const float2*)(sh_tl + tb))[lane];
                else           v = ((const float2*)(sh_g + gb))[lane - 16];
                for (int r = cw; r < NREP; r += 6) {
                    size_t row = (size_t)(b * NREP + r);
                    if (lane < 16)
                        ((float2*)(out + row * NBINS + tb))[lane] = v;
                    else
                        ((float2*)(outG + row * TSIM + gb))[lane - 16] = v;
                }
            }
        }
    }

    __syncthreads();
    // epilogue: segment 39 (t = 1248, 1249), one repeat per thread
    {
        size_t row = (size_t)(b * NREP) + tid;
        float2 vt = *(const float2*)(sh_tl + 1498);
        float2 vg = *(const float2*)(sh_g + 1248);
        *(float2*)(out + row * NBINS + 1498) = vt;
        *(float2*)(outG + row * TSIM + 1248) = vg;
    }
}

// ---------------------------------------------------------------------------
extern "C" void kernel_launch(void* const* d_in, const int* in_sizes, int n_in,
                              void* d_out, int out_size) {
    const float* A    = (const float*)d_in[0];  // (128, 2048)
    const float* st   = (const float*)d_in[1];  // (1500,)
    const float* init = (const float*)d_in[2];  // (128, 250)
    int off = (n_in >= 8) ? 1 : 0;              // skip n_repeats scalar if present
    const float* sf = (const float*)d_in[3 + off];  // (2048,)
    const float* tf = (const float*)d_in[4 + off];  // (250,)
    const float* fb = (const float*)d_in[5 + off];  // (250,)
    const float* bi = (const float*)d_in[6 + off];  // (1,)

    k_spat<<<B, 256>>>(A, sf);
    k_time<<<(LGS + 127) / 128, 128>>>(st, tf);
    k_recur<<<B, 256>>>(init, fb, bi, (float*)d_out);
}

// round 6
// speedup vs baseline: 1.1343x; 1.0589x over previous
#include <cuda_runtime.h>

// Problem constants (fixed by setup_inputs)
#define B     128
#define NPIX  2048
#define NBINS 1500
#define NBF   250
#define NREP  256
#define LGS   1251   // n_bins - n_bins_filter + 1
#define TSIM  1250   // len_bins_sim
#define NBLK  40     // ceil(TSIM/32)
#define N1    ((size_t)B * NREP * NBINS)   // start of gensig region in d_out

// Scratch (device globals; no dynamic allocation allowed)
__device__ float g_filt_spat[B];
__device__ float g_filt_time[LGS + 1];

__device__ __forceinline__ float fsig(float x) {
    // 1/(1+exp(-x)) via MUFU ex2 + rcp (rel err ~1e-6)
    return __fdividef(1.0f, 1.0f + __expf(-x));
}

// ---------------------------------------------------------------------------
// Prelude (one kernel): blocks 0..127 -> filt_spat rows; 128..132 -> filt_time
// ---------------------------------------------------------------------------
__global__ void k_pre(const float* __restrict__ A, const float* __restrict__ sf,
                      const float* __restrict__ st, const float* __restrict__ tf) {
    int tid = threadIdx.x;
    if (blockIdx.x < B) {
        // filt_spat[b] = dot(A[b,:], sf), float4-vectorized
        __shared__ float red[256];
        int b = blockIdx.x;
        const float4* row = (const float4*)(A + (size_t)b * NPIX);
        const float4* sf4 = (const float4*)sf;
        float s = 0.f;
        #pragma unroll
        for (int p = tid; p < NPIX / 4; p += 256) {
            float4 a = row[p], f = sf4[p];
            s += a.x * f.x + a.y * f.y + a.z * f.z + a.w * f.w;
        }
        red[tid] = s;
        __syncthreads();
        for (int o = 128; o > 0; o >>= 1) {
            if (tid < o) red[tid] += red[tid + o];
            __syncthreads();
        }
        if (tid == 0) g_filt_spat[b] = red[0];
    } else {
        // filt_time[t] = valid cross-correlation of stim_time with tf
        __shared__ float shtf[NBF];
        for (int j = tid; j < NBF; j += 256) shtf[j] = tf[j];
        __syncthreads();
        int t = (blockIdx.x - B) * 256 + tid;
        if (t < LGS) {
            float s = 0.f;
            #pragma unroll 5
            for (int j = 0; j < NBF; j++) s += st[t + j] * shtf[j];
            g_filt_time[t] = s;
        }
    }
}

// ---------------------------------------------------------------------------
// FUSED recurrence + decoupled broadcast writer. 128 CTAs x 256 threads.
//   warp 7   : serial chain (highest arbiter priority), 32 steps/iteration
//   warp 6   : pipelined precompute of next block's history-only partials
//   warps 0-5: stream finished segments to all 256 repeats, paced by a
//              shared-memory progress flag (chain never waits for stores)
//
// Timeline coords: tl[k]=init[k] for k<250, tl[250+t]=spike_t.
// fb_t = sum_{j=0..249} tl[t+j] * f[j].
// For block at T0, lane i (t=T0+i):
//   - taps j in [0, 217-i]   : spikes through block m-2 -> warp-6 precompute
//   - taps j in [218-i,249-i]: block m-1 spikes         -> 32-tap register fixup
//   - taps j in [250-i,249]  : in-block spikes          -> serial shfl chain
// ---------------------------------------------------------------------------
__global__ __launch_bounds__(256, 1) void k_recur(const float* __restrict__ init,
                                                  const float* __restrict__ fbf,
                                                  const float* __restrict__ bias,
                                                  float* __restrict__ out) {
    __shared__ __align__(16) float sh_tl[1504];   // timeline (init + spikes)
    __shared__ __align__(16) float sh_f[288];     // filter, zero-padded [250..287]
    __shared__ __align__(16) float sh_g[1280];    // drive g_t; overwritten w/ gensig_t
    __shared__ float sh_pre[2][32];
    __shared__ int   sh_prog;                     // segments produced (0..NBLK)

    int b = blockIdx.x, tid = threadIdx.x;
    int warp = tid >> 5, lane = tid & 31;
    float* outG = out + N1;
    volatile int* prog = &sh_prog;

    // --- setup ---
    if (tid == 0) sh_prog = 0;
    if (tid < NBF) { sh_tl[tid] = init[b * NBF + tid]; sh_f[tid] = fbf[tid]; }
    else if (tid < 288) sh_f[tid] = 0.f;
    {
        float fs = g_filt_spat[b], bv = bias[0];
        for (int j = tid; j < 1280; j += 256)
            sh_g[j] = (j < TSIM) ? fmaf(fs, g_filt_time[j], bv) : 0.f;
    }
    __syncthreads();

    if (warp == 7) {
        // ---------------- serial chain ----------------
        float fv[32], fr[32];   // statically indexed only
        #pragma unroll
        for (int k = 0; k < 32; k++) {
            fv[k] = sh_f[250 - lane + k];   // zero for k >= lane
            fr[k] = sh_f[218 - lane + k];
        }
        // block-0 precompute: all taps from initial history (j < 250-lane)
        {
            int lim = 250 - lane;
            float a0 = 0, a1 = 0, a2 = 0, a3 = 0;
            int j = 0;
            for (; j + 4 <= lim; j += 4) {
                a0 = fmaf(sh_tl[lane + j],     sh_f[j],     a0);
                a1 = fmaf(sh_tl[lane + j + 1], sh_f[j + 1], a1);
                a2 = fmaf(sh_tl[lane + j + 2], sh_f[j + 2], a2);
                a3 = fmaf(sh_tl[lane + j + 3], sh_f[j + 3], a3);
            }
            for (; j < lim; j++) a0 = fmaf(sh_tl[lane + j], sh_f[j], a0);
            sh_pre[0][lane] = (a0 + a1) + (a2 + a3);
        }

        for (int m = 0; m < NBLK; m++) {
            asm volatile("bar.sync 1, 64;" ::: "memory");  // warps 6+7 only
            int T0 = m * 32, t = T0 + lane;
            float part = sh_pre[m & 1][lane] + sh_g[t];

            if (m > 0) {
                int base = 250 + T0 - 32;   // previous block's 32 spikes
                float a0 = 0, a1 = 0, a2 = 0, a3 = 0;
                #pragma unroll
                for (int k = 0; k < 32; k += 4) {
                    a0 = fmaf(sh_tl[base + k],     fr[k],     a0);
                    a1 = fmaf(sh_tl[base + k + 1], fr[k + 1], a1);
                    a2 = fmaf(sh_tl[base + k + 2], fr[k + 2], a2);
                    a3 = fmaf(sh_tl[base + k + 3], fr[k + 3], a3);
                }
                part += (a0 + a1) + (a2 + a3);
            }

            // branchless chain: every lane evaluates sigmoid; shfl picks lane k.
            // fv[k]==0 for k>=lane, so each lane's part freezes at its own step.
            // (last block: lanes >= kmax compute garbage but are never stored;
            //  sh_g is zero-padded and all sh_tl/sh_pre reads stay in bounds)
            #pragma unroll
            for (int k = 0; k < 32; k++) {
                float cand = fsig(part);
                float s = __shfl_sync(0xffffffffu, cand, k);
                part = fmaf(s, fv[k], part);
            }

            int kmax = TSIM - T0; if (kmax > 32) kmax = 32;
            if (lane < kmax) {
                sh_tl[250 + t] = fsig(part);   // spike_t
                sh_g[t] = part;                // gensig_t (drive already consumed)
            }
            // publish segment m to copy warps
            __syncwarp();
            if (lane == 0) { __threadfence_block(); *prog = m + 1; }
        }
    } else if (warp == 6) {
        // ---------------- pipelined precompute ----------------
        for (int m = 0; m < NBLK; m++) {
            asm volatile("bar.sync 1, 64;" ::: "memory");
            if (m + 1 < NBLK) {
                int T0n = m * 32 + 32;
                int lim = 218 - lane;
                float a0 = 0, a1 = 0, a2 = 0, a3 = 0;
                int j = 0;
                for (; j + 4 <= lim; j += 4) {
                    a0 = fmaf(sh_tl[T0n + lane + j],     sh_f[j],     a0);
                    a1 = fmaf(sh_tl[T0n + lane + j + 1], sh_f[j + 1], a1);
                    a2 = fmaf(sh_tl[T0n + lane + j + 2], sh_f[j + 2], a2);
                    a3 = fmaf(sh_tl[T0n + lane + j + 3], sh_f[j + 3], a3);
                }
                for (; j < lim; j++) a0 = fmaf(sh_tl[T0n + lane + j], sh_f[j], a0);
                sh_pre[(m + 1) & 1][lane] = (a0 + a1) + (a2 + a3);
            }
        }
    } else {
        // ---------------- copy warps 0..5 ----------------
        int cw = warp;

        // init section: 250 floats = 125 float2 per repeat (no dependency)
        {
            const float2* src = (const float2*)sh_tl;
            int e0 = lane, e1 = lane + 32, e2 = lane + 64, e3 = lane + 96;
            float2 v0 = src[e0], v1 = src[e1], v2 = src[e2];
            float2 v3; if (e3 < 125) v3 = src[e3];
            for (int r = cw; r < NREP; r += 6) {
                float2* dst = (float2*)(out + ((size_t)(b * NREP + r)) * NBINS);
                dst[e0] = v0; dst[e1] = v1; dst[e2] = v2;
                if (e3 < 125) dst[e3] = v3;
            }
        }

        for (int seg = 0; seg < NBLK; seg++) {
            while (*prog <= seg) __nanosleep(128);
            __threadfence_block();

            if (seg < NBLK - 1) {
                int tb = 250 + seg * 32;          // even -> float2-safe
                int gb = seg * 32;
                float2 v;
                if (lane < 16) v = ((const float2*)(sh_tl + tb))[lane];
                else           v = ((const float2*)(sh_g + gb))[lane - 16];
                for (int r = cw; r < NREP; r += 6) {
                    size_t row = (size_t)(b * NREP + r);
                    if (lane < 16)
                        ((float2*)(out + row * NBINS + tb))[lane] = v;
                    else
                        ((float2*)(outG + row * TSIM + gb))[lane - 16] = v;
                }
            } else {
                // segment 39: only t = 1248,1249
                float2 vt = *(const float2*)(sh_tl + 1498);
                float2 vg = *(const float2*)(sh_g + 1248);
                for (int r = cw; r < NREP; r += 6) {
                    size_t row = (size_t)(b * NREP + r);
                    if (lane == 0) *(float2*)(out + row * NBINS + 1498) = vt;
                    if (lane == 1) *(float2*)(outG + row * TSIM + 1248) = vg;
                }
            }
        }
    }
}

// ---------------------------------------------------------------------------
extern "C" void kernel_launch(void* const* d_in, const int* in_sizes, int n_in,
                              void* d_out, int out_size) {
    const float* A    = (const float*)d_in[0];  // (128, 2048)
    const float* st   = (const float*)d_in[1];  // (1500,)
    const float* init = (const float*)d_in[2];  // (128, 250)
    int off = (n_in >= 8) ? 1 : 0;              // skip n_repeats scalar if present
    const float* sf = (const float*)d_in[3 + off];  // (2048,)
    const float* tf = (const float*)d_in[4 + off];  // (250,)
    const float* fb = (const float*)d_in[5 + off];  // (250,)
    const float* bi = (const float*)d_in[6 + off];  // (1,)

    k_pre<<<B + (LGS + 255) / 256, 256>>>(A, sf, st, tf);
    k_recur<<<B, 256>>>(init, fb, bi, (float*)d_out);
}

// round 7
// speedup vs baseline: 1.1627x; 1.0250x over previous
#include <cuda_runtime.h>

// Problem constants (fixed by setup_inputs)
#define B     128
#define NPIX  2048
#define NBINS 1500
#define NBF   250
#define NREP  256
#define TSIM  1250   // len_bins_sim
#define NBLK  40     // ceil(TSIM/32)
#define N1    ((size_t)B * NREP * NBINS)   // start of gensig region in d_out

#define NLOG2E (-1.4426950408889634f)
#define LN2    (0.6931471805599453f)

__device__ __forceinline__ float fex2(float x) {
    float r; asm("ex2.approx.ftz.f32 %0, %1;" : "=f"(r) : "f"(x)); return r;
}
__device__ __forceinline__ float frcp(float x) {
    float r; asm("rcp.approx.ftz.f32 %0, %1;" : "=f"(r) : "f"(x)); return r;
}

// ---------------------------------------------------------------------------
// ONE kernel: per-CTA prelude + serial recurrence + decoupled broadcast writer.
// 128 CTAs x 256 threads (8 warps):
//   setup    : all warps — load row/filters, spatial dot (block reduce),
//              1250-pt correlation (redundant per CTA, ~2us), build drive sh_g
//   warp 7   : serial chain in z-space (z = -log2e * gensig), 32 steps/iter
//   warp 6   : pipelined precompute of next block's history-only partials
//   warps 0-5: stream finished segments to all 256 repeats, paced by a
//              shared progress flag; branch-free strength-reduced STG loops
//
// Timeline coords: tl[k]=init[k] for k<250, tl[250+t]=spike_t.
// fb_t = sum_{j=0..249} tl[t+j] * f[j].
// For block at T0, lane i (t=T0+i):
//   - taps j in [0, 217-i]   : spikes through block m-2 -> warp-6 precompute
//   - taps j in [218-i,249-i]: block m-1 spikes         -> 32-tap register fixup
//   - taps j in [250-i,249]  : in-block spikes          -> serial shfl chain
// ---------------------------------------------------------------------------
__global__ __launch_bounds__(256, 1) void k_all(
    const float* __restrict__ A,    // (128, 2048)
    const float* __restrict__ st,   // (1500,)
    const float* __restrict__ init, // (128, 250)
    const float* __restrict__ sf,   // (2048,)
    const float* __restrict__ tf,   // (250,)
    const float* __restrict__ fbf,  // (250,)
    const float* __restrict__ bias, // (1,)
    float* __restrict__ out)
{
    __shared__ __align__(16) float sh_tl[1504];   // timeline (init + spikes)
    __shared__ __align__(16) float sh_f[288];     // feedback filter, zero-padded
    __shared__ __align__(16) float sh_g[1280];    // drive; overwritten w/ gensig
    __shared__ __align__(16) float sh_tc[256];    // timecourse filter
    __shared__ __align__(16) float sh_st[1504];   // stim_time
    __shared__ float red[256];
    __shared__ float sh_pre[2][32];
    __shared__ int   sh_prog;                     // segments produced (0..NBLK)

    int b = blockIdx.x, tid = threadIdx.x;
    int warp = tid >> 5, lane = tid & 31;
    float* outG = out + N1;

    // ------------------------- setup -------------------------
    if (tid == 0) sh_prog = 0;
    if (tid < NBF) {
        sh_f[tid]  = fbf[tid];
        sh_tc[tid] = tf[tid];
        sh_tl[tid] = init[b * NBF + tid];
    } else if (tid < 288) sh_f[tid] = 0.f;
    for (int j = tid; j < NBINS; j += 256) sh_st[j] = st[j];
    {   // spatial dot partials (2 float4 per thread)
        const float4* row4 = (const float4*)(A + (size_t)b * NPIX);
        const float4* sf4  = (const float4*)sf;
        float4 a0 = row4[tid], f0 = sf4[tid];
        float4 a1 = row4[tid + 256], f1 = sf4[tid + 256];
        red[tid] = a0.x*f0.x + a0.y*f0.y + a0.z*f0.z + a0.w*f0.w
                 + a1.x*f1.x + a1.y*f1.y + a1.z*f1.z + a1.w*f1.w;
    }
    __syncthreads();

    if (warp == 0) {   // reduce spatial dot
        float r = 0.f;
        #pragma unroll
        for (int k = 0; k < 8; k++) r += red[lane + 32 * k];
        #pragma unroll
        for (int o = 16; o > 0; o >>= 1) r += __shfl_xor_sync(0xffffffffu, r, o);
        if (lane == 0) red[0] = r;
    }
    // correlation: 5 t-values per thread (covers 0..1279)
    float corr[5];
    #pragma unroll
    for (int u = 0; u < 5; u++) {
        int t = tid + 256 * u;
        float a0 = 0, a1 = 0, a2 = 0, a3 = 0;
        if (t < TSIM) {
            for (int j = 0; j < 248; j += 4) {
                a0 = fmaf(sh_st[t + j],     sh_tc[j],     a0);
                a1 = fmaf(sh_st[t + j + 1], sh_tc[j + 1], a1);
                a2 = fmaf(sh_st[t + j + 2], sh_tc[j + 2], a2);
                a3 = fmaf(sh_st[t + j + 3], sh_tc[j + 3], a3);
            }
            a0 = fmaf(sh_st[t + 248], sh_tc[248], a0);
            a1 = fmaf(sh_st[t + 249], sh_tc[249], a1);
        }
        corr[u] = (a0 + a1) + (a2 + a3);
    }
    __syncthreads();
    {
        float fs = red[0], bv = bias[0];
        #pragma unroll
        for (int u = 0; u < 5; u++) {
            int t = tid + 256 * u;
            sh_g[t] = (t < TSIM) ? fmaf(fs, corr[u], bv) : 0.f;
        }
    }
    __syncthreads();

    // ------------------------- role split -------------------------
    if (warp == 7) {
        // ---------------- serial chain (z-space) ----------------
        float fw[32], fr[32];   // statically indexed only
        #pragma unroll
        for (int k = 0; k < 32; k++) {
            fw[k] = NLOG2E * sh_f[250 - lane + k];   // zero for k >= lane
            fr[k] = sh_f[218 - lane + k];
        }
        {   // block-0 precompute: all taps from initial history
            int lim = 250 - lane;
            float a0 = 0, a1 = 0, a2 = 0, a3 = 0;
            int j = 0;
            for (; j + 4 <= lim; j += 4) {
                a0 = fmaf(sh_tl[lane + j],     sh_f[j],     a0);
                a1 = fmaf(sh_tl[lane + j + 1], sh_f[j + 1], a1);
                a2 = fmaf(sh_tl[lane + j + 2], sh_f[j + 2], a2);
                a3 = fmaf(sh_tl[lane + j + 3], sh_f[j + 3], a3);
            }
            for (; j < lim; j++) a0 = fmaf(sh_tl[lane + j], sh_f[j], a0);
            sh_pre[0][lane] = (a0 + a1) + (a2 + a3);
        }

        for (int m = 0; m < NBLK; m++) {
            asm volatile("bar.sync 1, 64;" ::: "memory");  // warps 6+7 only
            int T0 = m * 32, t = T0 + lane;
            float part = sh_pre[m & 1][lane] + sh_g[t];

            if (m > 0) {   // fixup: previous block's 32 spikes
                int base = 250 + T0 - 32;
                float a0 = 0, a1 = 0, a2 = 0, a3 = 0;
                #pragma unroll
                for (int k = 0; k < 32; k += 4) {
                    a0 = fmaf(sh_tl[base + k],     fr[k],     a0);
                    a1 = fmaf(sh_tl[base + k + 1], fr[k + 1], a1);
                    a2 = fmaf(sh_tl[base + k + 2], fr[k + 2], a2);
                    a3 = fmaf(sh_tl[base + k + 3], fr[k + 3], a3);
                }
                part += (a0 + a1) + (a2 + a3);
            }

            // z-space chain: sigmoid(part) = rcp(1 + 2^z), z = -log2e*part.
            // fw[k]==0 for k>=lane, so each lane's z freezes at its own step;
            // sl after the loop is sigmoid of the frozen (final) gensig.
            float z = NLOG2E * part;
            float sl = 0.f;
            #pragma unroll
            for (int k = 0; k < 32; k++) {
                float e = fex2(z);
                sl = frcp(1.0f + e);
                float s = __shfl_sync(0xffffffffu, sl, k);
                z = fmaf(s, fw[k], z);
            }

            int kmax = TSIM - T0; if (kmax > 32) kmax = 32;
            if (lane < kmax) {
                sh_tl[250 + t] = sl;          // spike_t
                sh_g[t] = -LN2 * z;           // gensig_t
            }
            __syncwarp();
            if (lane == 0) { __threadfence_block(); *(volatile int*)&sh_prog = m + 1; }
        }
    } else if (warp == 6) {
        // ---------------- pipelined precompute ----------------
        for (int m = 0; m < NBLK; m++) {
            asm volatile("bar.sync 1, 64;" ::: "memory");
            if (m + 1 < NBLK) {
                int T0n = m * 32 + 32;
                int lim = 218 - lane;
                float a0 = 0, a1 = 0, a2 = 0, a3 = 0;
                int j = 0;
                for (; j + 4 <= lim; j += 4) {
                    a0 = fmaf(sh_tl[T0n + lane + j],     sh_f[j],     a0);
                    a1 = fmaf(sh_tl[T0n + lane + j + 1], sh_f[j + 1], a1);
                    a2 = fmaf(sh_tl[T0n + lane + j + 2], sh_f[j + 2], a2);
                    a3 = fmaf(sh_tl[T0n + lane + j + 3], sh_f[j + 3], a3);
                }
                for (; j < lim; j++) a0 = fmaf(sh_tl[T0n + lane + j], sh_f[j], a0);
                sh_pre[(m + 1) & 1][lane] = (a0 + a1) + (a2 + a3);
            }
        }
    } else {
        // ---------------- copy warps 0..5 ----------------
        int cw = warp;                               // 0..5
        int reps = (NREP - 1 - cw) / 6 + 1;          // 43 or 42
        size_t rowT0 = (size_t)(b * NREP + cw) * NBINS;
        size_t rowG0 = (size_t)(b * NREP + cw) * TSIM;
        volatile int* prog = &sh_prog;

        // init section: 250 floats = 125 float2 per repeat (no dependency)
        {
            const float2* s2 = (const float2*)sh_tl;
            float2 v0 = s2[lane], v1 = s2[lane + 32], v2 = s2[lane + 64];
            bool has3 = (lane + 96) < 125;
            float2 v3 = has3 ? s2[lane + 96] : make_float2(0.f, 0.f);
            float* base = out + rowT0;
            for (int i = 0; i < reps; i++) {
                float2* d = (float2*)base;
                __stcs(d + lane, v0);
                __stcs(d + lane + 32, v1);
                __stcs(d + lane + 64, v2);
                if (has3) __stcs(d + lane + 96, v3);
                base += (size_t)6 * NBINS;
            }
        }

        bool isT = lane < 16;
        int sub = isT ? lane : lane - 16;
        size_t stride = isT ? (size_t)6 * NBINS : (size_t)6 * TSIM;

        for (int seg = 0; seg < NBLK; seg++) {
            while (*prog <= seg) __nanosleep(64);
            __threadfence_block();

            int tb = 250 + seg * 32, gb = seg * 32;
            int w = TSIM - gb; if (w > 32) w = 32;   // 32, except last seg: 2
            if (sub < (w >> 1)) {
                float2 v = isT ? *(const float2*)(sh_tl + tb + 2 * sub)
                               : *(const float2*)(sh_g + gb + 2 * sub);
                float* base = isT ? out + rowT0 + tb + 2 * sub
                                  : outG + rowG0 + gb + 2 * sub;
                #pragma unroll 4
                for (int i = 0; i < reps; i++) {
                    __stcs((float2*)base, v);
                    base += stride;
                }
            }
        }
    }
}

// ---------------------------------------------------------------------------
extern "C" void kernel_launch(void* const* d_in, const int* in_sizes, int n_in,
                              void* d_out, int out_size) {
    const float* A    = (const float*)d_in[0];  // (128, 2048)
    const float* st   = (const float*)d_in[1];  // (1500,)
    const float* init = (const float*)d_in[2];  // (128, 250)
    int off = (n_in >= 8) ? 1 : 0;              // skip n_repeats scalar if present
    const float* sf = (const float*)d_in[3 + off];  // (2048,)
    const float* tf = (const float*)d_in[4 + off];  // (250,)
    const float* fb = (const float*)d_in[5 + off];  // (250,)
    const float* bi = (const float*)d_in[6 + off];  // (1,)

    k_all<<<B, 256>>>(A, st, init, sf, tf, fb, bi, (float*)d_out);
}